// round 8
// baseline (speedup 1.0000x reference)
#include <cuda_runtime.h>
#include <stdint.h>

__global__ void zero_out_kernel(float* __restrict__ out, int n) {
    int i = blockIdx.x * blockDim.x + threadIdx.x;
    float4* o4 = reinterpret_cast<float4*>(out);
    int n4 = n >> 2;
    if (i < n4) o4[i] = make_float4(0.f, 0.f, 0.f, 0.f);
}

__global__ void scatter_add_kernel(
    const float* __restrict__ beta,          // [1]
    const float* __restrict__ tnet_weights,  // [num_tnets]
    const int2*  __restrict__ tnet2pin,      // [num_tnets] pairs (src,dst), int32
    const int*   __restrict__ pin2node,      // [num_pins], int32
    float* __restrict__ out,                 // [num_nodes]
    int num_tnets)
{
    int i = blockIdx.x * blockDim.x + threadIdx.x;
    if (i >= num_tnets) return;

    float wb = __ldg(&tnet_weights[i]) * __ldg(beta);
    int2 pins = __ldg(&tnet2pin[i]);

    int n0 = __ldg(&pin2node[pins.x]);
    int n1 = __ldg(&pin2node[pins.y]);

    atomicAdd(out + n0, wb);
    atomicAdd(out + n1, wb);
}

extern "C" void kernel_launch(void* const* d_in, const int* in_sizes, int n_in,
                              void* d_out, int out_size)
{
    const float* beta     = (const float*)d_in[0];
    const float* tnet_w   = (const float*)d_in[1];
    const int*   flat_t2p = (const int*)d_in[2];
    const int*   pin2node = (const int*)d_in[3];
    float*       out      = (float*)d_out;

    int num_tnets = in_sizes[1];   // 8388608
    int num_nodes = out_size;      // 1048576

    // 1) zero the output (harness poisons it to 0xAA)
    {
        int n4 = num_nodes >> 2;
        int threads = 256;
        int blocks = (n4 + threads - 1) / threads;
        zero_out_kernel<<<blocks, threads>>>(out, num_nodes);
    }

    // 2) scatter-add with beta fused into the weight
    {
        int threads = 256;
        int blocks = (num_tnets + threads - 1) / threads;
        scatter_add_kernel<<<blocks, threads>>>(
            beta, tnet_w, (const int2*)flat_t2p, pin2node, out, num_tnets);
    }
}

// round 12
// speedup vs baseline: 1.0731x; 1.0731x over previous
#include <cuda_runtime.h>
#include <stdint.h>

__global__ void zero_out_kernel(float* __restrict__ out, int n) {
    int i = blockIdx.x * blockDim.x + threadIdx.x;
    float4* o4 = reinterpret_cast<float4*>(out);
    int n4 = n >> 2;
    if (i < n4) o4[i] = make_float4(0.f, 0.f, 0.f, 0.f);
}

// Gather load with evict_last L2 policy via cache-hint register
// (scalar .L2::evict_last modifier form is rejected by ptxas on sm_103a).
__device__ __forceinline__ int ldg_evict_last(const int* p, uint64_t policy) {
    int v;
    asm volatile("ld.global.nc.L2::cache_hint.b32 %0, [%1], %2;"
                 : "=r"(v) : "l"(p), "l"(policy));
    return v;
}

__global__ void scatter_add_kernel(
    const float*  __restrict__ beta,          // [1]
    const float2* __restrict__ tnet_weights,  // [num_tnets/2] as float2
    const int4*   __restrict__ tnet2pin,      // [num_tnets/2] two (src,dst) pairs
    const int*    __restrict__ pin2node,      // [num_pins], int32
    float* __restrict__ out,                  // [num_nodes]
    int num_pairs)                            // num_tnets/2
{
    int i = blockIdx.x * blockDim.x + threadIdx.x;
    if (i >= num_pairs) return;

    uint64_t policy;
    asm volatile("createpolicy.fractional.L2::evict_last.b64 %0, 1.0;"
                 : "=l"(policy));

    float b = __ldg(beta);
    // Streaming (evict-first) loads: don't pollute L2.
    float2 w  = __ldcs(&tnet_weights[i]);
    int4 pins = __ldcs(&tnet2pin[i]);

    float wb0 = w.x * b;
    float wb1 = w.y * b;

    // Random gathers, keep resident in L2.
    int n0 = ldg_evict_last(&pin2node[pins.x], policy);
    int n1 = ldg_evict_last(&pin2node[pins.y], policy);
    int n2 = ldg_evict_last(&pin2node[pins.z], policy);
    int n3 = ldg_evict_last(&pin2node[pins.w], policy);

    atomicAdd(out + n0, wb0);
    atomicAdd(out + n1, wb0);
    atomicAdd(out + n2, wb1);
    atomicAdd(out + n3, wb1);
}

extern "C" void kernel_launch(void* const* d_in, const int* in_sizes, int n_in,
                              void* d_out, int out_size)
{
    const float* beta     = (const float*)d_in[0];
    const float* tnet_w   = (const float*)d_in[1];
    const int*   flat_t2p = (const int*)d_in[2];
    const int*   pin2node = (const int*)d_in[3];
    float*       out      = (float*)d_out;

    int num_tnets = in_sizes[1];   // 8388608
    int num_nodes = out_size;      // 1048576
    int num_pairs = num_tnets >> 1;

    // 1) zero the output (harness poisons it to 0xAA)
    {
        int n4 = num_nodes >> 2;
        int threads = 256;
        int blocks = (n4 + threads - 1) / threads;
        zero_out_kernel<<<blocks, threads>>>(out, num_nodes);
    }

    // 2) scatter-add, beta fused, 2 arcs per thread
    {
        int threads = 256;
        int blocks = (num_pairs + threads - 1) / threads;
        scatter_add_kernel<<<blocks, threads>>>(
            beta, (const float2*)tnet_w, (const int4*)flat_t2p,
            pin2node, out, num_pairs);
    }
}

// round 13
// speedup vs baseline: 1.0733x; 1.0002x over previous
#include <cuda_runtime.h>
#include <stdint.h>

__global__ void zero_out_kernel(float* __restrict__ out, int n) {
    int i = blockIdx.x * blockDim.x + threadIdx.x;
    float4* o4 = reinterpret_cast<float4*>(out);
    int n4 = n >> 2;
    if (i < n4) o4[i] = make_float4(0.f, 0.f, 0.f, 0.f);
}

// Gather load with evict_last L2 policy via cache-hint register
// (scalar .L2::evict_last modifier form is rejected by ptxas on sm_103a).
__device__ __forceinline__ int ldg_evict_last(const int* p, uint64_t policy) {
    int v;
    asm volatile("ld.global.nc.L2::cache_hint.b32 %0, [%1], %2;"
                 : "=r"(v) : "l"(p), "l"(policy));
    return v;
}

__global__ void scatter_add_kernel(
    const float*  __restrict__ beta,          // [1]
    const float2* __restrict__ tnet_weights,  // [num_tnets/2] as float2
    const int4*   __restrict__ tnet2pin,      // [num_tnets/2] two (src,dst) pairs
    const int*    __restrict__ pin2node,      // [num_pins], int32
    float* __restrict__ out,                  // [num_nodes]
    int num_pairs)                            // num_tnets/2
{
    int i = blockIdx.x * blockDim.x + threadIdx.x;
    if (i >= num_pairs) return;

    uint64_t policy;
    asm volatile("createpolicy.fractional.L2::evict_last.b64 %0, 1.0;"
                 : "=l"(policy));

    float b = __ldg(beta);
    // Streaming (evict-first) loads: don't pollute L2.
    float2 w  = __ldcs(&tnet_weights[i]);
    int4 pins = __ldcs(&tnet2pin[i]);

    float wb0 = w.x * b;
    float wb1 = w.y * b;

    // Random gathers, keep resident in L2.
    int n0 = ldg_evict_last(&pin2node[pins.x], policy);
    int n1 = ldg_evict_last(&pin2node[pins.y], policy);
    int n2 = ldg_evict_last(&pin2node[pins.z], policy);
    int n3 = ldg_evict_last(&pin2node[pins.w], policy);

    atomicAdd(out + n0, wb0);
    atomicAdd(out + n1, wb0);
    atomicAdd(out + n2, wb1);
    atomicAdd(out + n3, wb1);
}

extern "C" void kernel_launch(void* const* d_in, const int* in_sizes, int n_in,
                              void* d_out, int out_size)
{
    const float* beta     = (const float*)d_in[0];
    const float* tnet_w   = (const float*)d_in[1];
    const int*   flat_t2p = (const int*)d_in[2];
    const int*   pin2node = (const int*)d_in[3];
    float*       out      = (float*)d_out;

    int num_tnets = in_sizes[1];   // 8388608
    int num_nodes = out_size;      // 1048576
    int num_pairs = num_tnets >> 1;

    // 1) zero the output (harness poisons it to 0xAA)
    {
        int n4 = num_nodes >> 2;
        int threads = 256;
        int blocks = (n4 + threads - 1) / threads;
        zero_out_kernel<<<blocks, threads>>>(out, num_nodes);
    }

    // 2) scatter-add, beta fused, 2 arcs per thread
    {
        int threads = 256;
        int blocks = (num_pairs + threads - 1) / threads;
        scatter_add_kernel<<<blocks, threads>>>(
            beta, (const float2*)tnet_w, (const int4*)flat_t2p,
            pin2node, out, num_pairs);
    }
}